// round 1
// baseline (speedup 1.0000x reference)
#include <cuda_runtime.h>
#include <cuda_bf16.h>
#include <math.h>

#define N_SRC 50000
#define N_DST 50000
#define E_NUM 800000
#define F_IN 128
#define HD 128            // H*D
#define NEG_SLOPE 0.2f

// ---------------- scratch (static device allocations are allowed) -------------
__device__ __align__(16) float g_Psrc[(size_t)N_SRC * HD];   // src_feat @ W_src[:128]
__device__ __align__(16) float g_nh  [(size_t)N_DST * HD];   // dst_feat @ W_dst
__device__ __align__(16) float g_Pe  [(size_t)E_NUM * HD];   // edge_feat @ W_src[128:]
__device__ int g_count [N_DST];
__device__ int g_offset[N_DST + 1];
__device__ int g_cursor[N_DST];
__device__ int g_elist [E_NUM];

// ---------------- tiny utility kernels ---------------------------------------
__global__ void zero_counts_kernel() {
    int i = blockIdx.x * blockDim.x + threadIdx.x;
    if (i < N_DST) g_count[i] = 0;
}

__global__ void count_kernel(const int* __restrict__ dst_idx) {
    int e = blockIdx.x * blockDim.x + threadIdx.x;
    if (e < E_NUM) atomicAdd(&g_count[dst_idx[e]], 1);
}

// single-block exclusive scan over g_count -> g_offset / g_cursor
__global__ void scan_kernel() {
    __shared__ int warpsums[32];
    __shared__ int s_running;
    int tid = threadIdx.x;
    int lane = tid & 31, warp = tid >> 5;
    if (tid == 0) s_running = 0;
    __syncthreads();
    for (int base = 0; base < N_DST; base += 1024) {
        int i = base + tid;
        int v = (i < N_DST) ? g_count[i] : 0;
        int x = v;
        #pragma unroll
        for (int o = 1; o < 32; o <<= 1) {
            int t = __shfl_up_sync(0xffffffffu, x, o);
            if (lane >= o) x += t;
        }
        if (lane == 31) warpsums[warp] = x;
        __syncthreads();
        if (warp == 0) {
            int w = warpsums[lane];
            #pragma unroll
            for (int o = 1; o < 32; o <<= 1) {
                int t = __shfl_up_sync(0xffffffffu, w, o);
                if (lane >= o) w += t;
            }
            warpsums[lane] = w;
        }
        __syncthreads();
        int incl = x + (warp > 0 ? warpsums[warp - 1] : 0);
        int excl = incl - v + s_running;
        if (i < N_DST) { g_offset[i] = excl; g_cursor[i] = excl; }
        __syncthreads();
        if (tid == 1023) s_running += warpsums[31];
        __syncthreads();
    }
    if (tid == 0) g_offset[N_DST] = s_running;
}

__global__ void scatter_kernel(const int* __restrict__ dst_idx) {
    int e = blockIdx.x * blockDim.x + threadIdx.x;
    if (e < E_NUM) {
        int p = atomicAdd(&g_cursor[dst_idx[e]], 1);
        g_elist[p] = e;
    }
}

// ---------------- fp32 SGEMM:  C[M,128] = A[M,128] @ B[128,128] ---------------
#define BM 128
#define BN 128
#define BK 16
#define TM 8
#define TN 8

__global__ __launch_bounds__(256, 2)
void sgemm128_kernel(const float* __restrict__ A, const float* __restrict__ B,
                     float* __restrict__ C, int M) {
    __shared__ float As[BK][BM + 4];
    __shared__ float Bs[BK][BN];
    int tid = threadIdx.x;
    int tx = tid & 15;          // 0..15
    int ty = tid >> 4;          // 0..15
    int blockRow = blockIdx.x * BM;

    float acc[TM][TN];
    #pragma unroll
    for (int i = 0; i < TM; i++)
        #pragma unroll
        for (int j = 0; j < TN; j++) acc[i][j] = 0.f;

    int a_r = tid >> 2;         // 0..63
    int a_c = tid & 3;          // float4 slot within 16 k's
    int b_r = tid >> 5;         // 0..7
    int b_c = tid & 31;         // float4 col

    for (int k0 = 0; k0 < F_IN; k0 += BK) {
        #pragma unroll
        for (int i = 0; i < 2; i++) {
            int r = a_r + i * 64;
            int gr = blockRow + r;
            float4 v = make_float4(0.f, 0.f, 0.f, 0.f);
            if (gr < M) v = *(const float4*)&A[(size_t)gr * F_IN + k0 + a_c * 4];
            As[a_c * 4 + 0][r] = v.x;
            As[a_c * 4 + 1][r] = v.y;
            As[a_c * 4 + 2][r] = v.z;
            As[a_c * 4 + 3][r] = v.w;
        }
        #pragma unroll
        for (int i = 0; i < 2; i++) {
            int r = b_r + i * 8;
            float4 v = *(const float4*)&B[(size_t)(k0 + r) * BN + b_c * 4];
            *(float4*)&Bs[r][b_c * 4] = v;
        }
        __syncthreads();
        #pragma unroll
        for (int kk = 0; kk < BK; kk++) {
            float a_frag[TM], b_frag[TN];
            #pragma unroll
            for (int i = 0; i < TM; i++) a_frag[i] = As[kk][ty * TM + i];
            #pragma unroll
            for (int j = 0; j < TN; j++) b_frag[j] = Bs[kk][tx * TN + j];
            #pragma unroll
            for (int i = 0; i < TM; i++)
                #pragma unroll
                for (int j = 0; j < TN; j++)
                    acc[i][j] = fmaf(a_frag[i], b_frag[j], acc[i][j]);
        }
        __syncthreads();
    }

    #pragma unroll
    for (int i = 0; i < TM; i++) {
        int gr = blockRow + ty * TM + i;
        if (gr < M) {
            #pragma unroll
            for (int j = 0; j < TN; j += 4) {
                *(float4*)&C[(size_t)gr * BN + tx * TN + j] =
                    make_float4(acc[i][j], acc[i][j+1], acc[i][j+2], acc[i][j+3]);
            }
        }
    }
}

// ---------------- per-destination online-softmax aggregation ------------------
// one block (128 threads) per dst node; thread c owns channel c.
__global__ __launch_bounds__(128)
void aggregate_kernel(const int* __restrict__ src_idx,
                      const float* __restrict__ bias,
                      float* __restrict__ out) {
    int d = blockIdx.x;
    int c = threadIdx.x;
    int beg = g_offset[d];
    int end = g_offset[d + 1];
    int deg = end - beg;

    float nhc = g_nh[(size_t)d * HD + c];
    float Mv = -3.0e38f;
    float S = 0.f;
    float Acc = 0.f;

    __shared__ int se[64];
    __shared__ int ss[64];

    for (int base = 0; base < deg; base += 64) {
        int n = min(64, deg - base);
        if (c < n) {
            int e = g_elist[beg + base + c];
            se[c] = e;
            ss[c] = src_idx[e];
        }
        __syncthreads();
        #pragma unroll 4
        for (int i = 0; i < n; i++) {
            float m = g_Pe[(size_t)se[i] * HD + c] + g_Psrc[(size_t)ss[i] * HD + c];
            float sc = m + nhc;
            sc = sc > 0.f ? sc : NEG_SLOPE * sc;
            if (sc > Mv) {
                float r = __expf(Mv - sc);   // 0 on first iter (Mv = -3e38)
                S *= r;
                Acc *= r;
                Mv = sc;
            }
            float w = __expf(sc - Mv);
            S += w;
            Acc += m * w;
        }
        __syncthreads();
    }

    float res = (deg > 0) ? (Acc / S) : 0.f;
    out[(size_t)d * HD + c] = res + bias[c];
}

// ---------------- launch ------------------------------------------------------
extern "C" void kernel_launch(void* const* d_in, const int* in_sizes, int n_in,
                              void* d_out, int out_size) {
    const float* src_feat  = (const float*)d_in[0];
    const float* dst_feat  = (const float*)d_in[1];
    const float* edge_feat = (const float*)d_in[2];
    const float* W_src     = (const float*)d_in[3];   // [256,128]
    const float* W_dst     = (const float*)d_in[4];   // [128,128]
    const float* bias      = (const float*)d_in[5];   // [128]
    const int*   src_idx   = (const int*)d_in[6];
    const int*   dst_idx   = (const int*)d_in[7];
    float* out = (float*)d_out;

    // resolve device-symbol addresses for GEMM outputs (host side, no stream ops)
    static float* p_Psrc = nullptr;
    static float* p_nh   = nullptr;
    static float* p_Pe   = nullptr;
    if (!p_Psrc) {
        cudaGetSymbolAddress((void**)&p_Psrc, g_Psrc);
        cudaGetSymbolAddress((void**)&p_nh,   g_nh);
        cudaGetSymbolAddress((void**)&p_Pe,   g_Pe);
    }

    // CSR build
    zero_counts_kernel<<<(N_DST + 255) / 256, 256>>>();
    count_kernel<<<(E_NUM + 255) / 256, 256>>>(dst_idx);
    scan_kernel<<<1, 1024>>>();
    scatter_kernel<<<(E_NUM + 255) / 256, 256>>>(dst_idx);

    // projections
    sgemm128_kernel<<<(N_SRC + BM - 1) / BM, 256>>>(src_feat, W_src, p_Psrc, N_SRC);
    sgemm128_kernel<<<(N_DST + BM - 1) / BM, 256>>>(dst_feat, W_dst, p_nh, N_DST);
    sgemm128_kernel<<<E_NUM / BM, 256>>>(edge_feat, W_src + F_IN * HD, p_Pe, E_NUM);

    // fused online-softmax aggregation
    aggregate_kernel<<<N_DST, 128>>>(src_idx, bias, out);
}

// round 3
// speedup vs baseline: 1.8548x; 1.8548x over previous
#include <cuda_runtime.h>
#include <cuda_bf16.h>
#include <cstdint>
#include <math.h>

#define N_SRC 50000
#define N_DST 50000
#define E_NUM 800000
#define F_IN 128
#define HD 128            // H*D
#define NEG_SLOPE 0.2f

// ---------------- scratch (static device allocations are allowed) -------------
__device__ __align__(16) float g_Psrc[(size_t)N_SRC * HD];   // src_feat @ W_src[:128]
__device__ __align__(16) float g_nh  [(size_t)N_DST * HD];   // dst_feat @ W_dst
__device__ __align__(16) float g_Pe  [(size_t)E_NUM * HD];   // edge_feat @ W_src[128:]
__device__ int g_count [N_DST];
__device__ int g_offset[N_DST + 1];
__device__ int g_cursor[N_DST];
__device__ int g_elist [E_NUM];

// ---------------- helpers -----------------------------------------------------
__device__ __forceinline__ uint32_t smem_u32(const void* p) {
    uint32_t a;
    asm("{ .reg .u64 t; cvta.to.shared.u64 t, %1; cvt.u32.u64 %0, t; }"
        : "=r"(a) : "l"(p));
    return a;
}

__device__ __forceinline__ uint32_t f2tf32(float f) {
    uint32_t t;
    asm("cvt.rna.tf32.f32 %0, %1;" : "=r"(t) : "f"(f));
    return t;
}

// ---------------- tiny utility kernels ---------------------------------------
__global__ void zero_counts_kernel() {
    int i = blockIdx.x * blockDim.x + threadIdx.x;
    if (i < N_DST) g_count[i] = 0;
}

__global__ void count_kernel(const int* __restrict__ dst_idx) {
    int e = blockIdx.x * blockDim.x + threadIdx.x;
    if (e < E_NUM) atomicAdd(&g_count[dst_idx[e]], 1);
}

__global__ void scan_kernel() {
    __shared__ int warpsums[32];
    __shared__ int s_running;
    int tid = threadIdx.x;
    int lane = tid & 31, warp = tid >> 5;
    if (tid == 0) s_running = 0;
    __syncthreads();
    for (int base = 0; base < N_DST; base += 1024) {
        int i = base + tid;
        int v = (i < N_DST) ? g_count[i] : 0;
        int x = v;
        #pragma unroll
        for (int o = 1; o < 32; o <<= 1) {
            int t = __shfl_up_sync(0xffffffffu, x, o);
            if (lane >= o) x += t;
        }
        if (lane == 31) warpsums[warp] = x;
        __syncthreads();
        if (warp == 0) {
            int w = warpsums[lane];
            #pragma unroll
            for (int o = 1; o < 32; o <<= 1) {
                int t = __shfl_up_sync(0xffffffffu, w, o);
                if (lane >= o) w += t;
            }
            warpsums[lane] = w;
        }
        __syncthreads();
        int incl = x + (warp > 0 ? warpsums[warp - 1] : 0);
        int excl = incl - v + s_running;
        if (i < N_DST) { g_offset[i] = excl; g_cursor[i] = excl; }
        __syncthreads();
        if (tid == 1023) s_running += warpsums[31];
        __syncthreads();
    }
    if (tid == 0) g_offset[N_DST] = s_running;
}

__global__ void scatter_kernel(const int* __restrict__ dst_idx) {
    int e = blockIdx.x * blockDim.x + threadIdx.x;
    if (e < E_NUM) {
        int p = atomicAdd(&g_cursor[dst_idx[e]], 1);
        g_elist[p] = e;
    }
}

// ---------------- tf32 mma.sync GEMM: C[M,128] = A[M,128] @ W[128,128] --------
// Bs: tf32 weights, word index = n*SB + k (conflict-free fragment loads)
// As: raw fp32 A chunk, word index = r*SA + kc (kc within 32-wide chunk)
#define SA 36
#define SB 132
#define BS_WORDS (128 * SB)              // 16896
#define AS_WORDS (128 * SA)              // 4608
#define GEMM_SMEM ((BS_WORDS + 2 * AS_WORDS) * 4)   // 104448 bytes

__global__ __launch_bounds__(256, 1)
void tf32_gemm_kernel(const float* __restrict__ A,
                      const float* __restrict__ W,    // [128 k][128 n] row-major
                      float* __restrict__ C, int M) {
    extern __shared__ uint32_t smem[];
    uint32_t* Bs = smem;
    uint32_t* As = smem + BS_WORDS;
    uint32_t sbase = smem_u32(smem);

    int tid = threadIdx.x;
    int lane = tid & 31, wid = tid >> 5;
    int gid = lane >> 2, tig = lane & 3;
    int warpM = wid >> 1, warpN = wid & 1;     // 4 (M) x 2 (N) warp grid
    long blockRow = (long)blockIdx.x * 128;

    // ---- load + convert W into Bs (one-time, L2-resident) ----
    #pragma unroll 8
    for (int i = 0; i < 64; i++) {
        int j = tid + i * 256;          // j = k*128 + n
        int k = j >> 7, n = j & 127;
        Bs[n * SB + k] = f2tf32(W[j]);
    }

    // ---- cp.async prefetch of A chunk ks into buffer buf ----
    auto prefetch = [&](int ks, int buf) {
        uint32_t dbase = sbase + (BS_WORDS + buf * AS_WORDS) * 4;
        #pragma unroll
        for (int i = 0; i < 4; i++) {
            int idx = tid + i * 256;    // 0..1023
            int r = idx >> 3, c4 = idx & 7;
            long row = blockRow + r;
            bool valid = row < M;
            const float* src = A + (valid ? row : 0) * (long)F_IN + ks * 32 + c4 * 4;
            uint32_t daddr = dbase + (r * SA + c4 * 4) * 4;
            int sz = valid ? 16 : 0;
            asm volatile("cp.async.cg.shared.global [%0], [%1], 16, %2;"
                         :: "r"(daddr), "l"(src), "r"(sz) : "memory");
        }
        asm volatile("cp.async.commit_group;" ::: "memory");
    };

    prefetch(0, 0);
    prefetch(1, 1);

    float acc[2][8][4];
    #pragma unroll
    for (int mt = 0; mt < 2; mt++)
        #pragma unroll
        for (int nt = 0; nt < 8; nt++)
            #pragma unroll
            for (int j = 0; j < 4; j++) acc[mt][nt][j] = 0.f;

    #pragma unroll
    for (int ks = 0; ks < 4; ks++) {
        if (ks < 3) asm volatile("cp.async.wait_group 1;" ::: "memory");
        else        asm volatile("cp.async.wait_group 0;" ::: "memory");
        __syncthreads();

        uint32_t* Ab = As + (ks & 1) * AS_WORDS;
        #pragma unroll
        for (int kk = 0; kk < 4; kk++) {
            int k = kk * 8;
            uint32_t a[2][4];
            #pragma unroll
            for (int mt = 0; mt < 2; mt++) {
                int r = warpM * 32 + mt * 16 + gid;
                uint32_t f0 = Ab[r * SA + k + tig];
                uint32_t f1 = Ab[(r + 8) * SA + k + tig];
                uint32_t f2 = Ab[r * SA + k + tig + 4];
                uint32_t f3 = Ab[(r + 8) * SA + k + tig + 4];
                a[mt][0] = f2tf32(__uint_as_float(f0));
                a[mt][1] = f2tf32(__uint_as_float(f1));
                a[mt][2] = f2tf32(__uint_as_float(f2));
                a[mt][3] = f2tf32(__uint_as_float(f3));
            }
            #pragma unroll
            for (int nt = 0; nt < 8; nt++) {
                int n = warpN * 64 + nt * 8 + gid;
                uint32_t b0 = Bs[n * SB + ks * 32 + k + tig];
                uint32_t b1 = Bs[n * SB + ks * 32 + k + tig + 4];
                #pragma unroll
                for (int mt = 0; mt < 2; mt++) {
                    asm volatile(
                        "mma.sync.aligned.m16n8k8.row.col.f32.tf32.tf32.f32 "
                        "{%0,%1,%2,%3}, {%4,%5,%6,%7}, {%8,%9}, {%0,%1,%2,%3};"
                        : "+f"(acc[mt][nt][0]), "+f"(acc[mt][nt][1]),
                          "+f"(acc[mt][nt][2]), "+f"(acc[mt][nt][3])
                        : "r"(a[mt][0]), "r"(a[mt][1]), "r"(a[mt][2]), "r"(a[mt][3]),
                          "r"(b0), "r"(b1));
                }
            }
        }
        __syncthreads();
        if (ks < 2) prefetch(ks + 2, ks & 1);
    }

    // ---- epilogue: direct stores (float2 per c-pair) ----
    #pragma unroll
    for (int mt = 0; mt < 2; mt++) {
        long r0 = blockRow + warpM * 32 + mt * 16 + gid;
        long r1 = r0 + 8;
        #pragma unroll
        for (int nt = 0; nt < 8; nt++) {
            int n = warpN * 64 + nt * 8 + tig * 2;
            if (r0 < M) {
                float2 v = make_float2(acc[mt][nt][0], acc[mt][nt][1]);
                *(float2*)&C[r0 * HD + n] = v;
            }
            if (r1 < M) {
                float2 v = make_float2(acc[mt][nt][2], acc[mt][nt][3]);
                *(float2*)&C[r1 * HD + n] = v;
            }
        }
    }
}

// ---------------- per-destination online-softmax aggregation ------------------
__global__ __launch_bounds__(128)
void aggregate_kernel(const int* __restrict__ src_idx,
                      const float* __restrict__ bias,
                      float* __restrict__ out) {
    int d = blockIdx.x;
    int c = threadIdx.x;
    int beg = g_offset[d];
    int end = g_offset[d + 1];
    int deg = end - beg;

    float nhc = g_nh[(size_t)d * HD + c];
    float Mv = -3.0e38f;
    float S = 0.f;
    float Acc = 0.f;

    __shared__ int se[64];
    __shared__ int ss[64];

    for (int base = 0; base < deg; base += 64) {
        int n = min(64, deg - base);
        if (c < n) {
            int e = g_elist[beg + base + c];
            se[c] = e;
            ss[c] = src_idx[e];
        }
        __syncthreads();
        #pragma unroll 4
        for (int i = 0; i < n; i++) {
            float m = g_Pe[(size_t)se[i] * HD + c] + g_Psrc[(size_t)ss[i] * HD + c];
            float sc = m + nhc;
            sc = sc > 0.f ? sc : NEG_SLOPE * sc;
            if (sc > Mv) {
                float r = __expf(Mv - sc);
                S *= r;
                Acc *= r;
                Mv = sc;
            }
            float w = __expf(sc - Mv);
            S += w;
            Acc += m * w;
        }
        __syncthreads();
    }

    float res = (deg > 0) ? (Acc / S) : 0.f;
    out[(size_t)d * HD + c] = res + bias[c];
}

// ---------------- launch ------------------------------------------------------
extern "C" void kernel_launch(void* const* d_in, const int* in_sizes, int n_in,
                              void* d_out, int out_size) {
    const float* src_feat  = (const float*)d_in[0];
    const float* dst_feat  = (const float*)d_in[1];
    const float* edge_feat = (const float*)d_in[2];
    const float* W_src     = (const float*)d_in[3];   // [256,128]
    const float* W_dst     = (const float*)d_in[4];   // [128,128]
    const float* bias      = (const float*)d_in[5];   // [128]
    const int*   src_idx   = (const int*)d_in[6];
    const int*   dst_idx   = (const int*)d_in[7];
    float* out = (float*)d_out;

    static float* p_Psrc = nullptr;
    static float* p_nh   = nullptr;
    static float* p_Pe   = nullptr;
    if (!p_Psrc) {
        cudaGetSymbolAddress((void**)&p_Psrc, g_Psrc);
        cudaGetSymbolAddress((void**)&p_nh,   g_nh);
        cudaGetSymbolAddress((void**)&p_Pe,   g_Pe);
        cudaFuncSetAttribute(tf32_gemm_kernel,
                             cudaFuncAttributeMaxDynamicSharedMemorySize, GEMM_SMEM);
    }

    // CSR build
    zero_counts_kernel<<<(N_DST + 255) / 256, 256>>>();
    count_kernel<<<(E_NUM + 255) / 256, 256>>>(dst_idx);
    scan_kernel<<<1, 1024>>>();
    scatter_kernel<<<(E_NUM + 255) / 256, 256>>>(dst_idx);

    // projections on tensor cores (tf32, fp32 accumulate)
    tf32_gemm_kernel<<<(N_SRC + 127) / 128, 256, GEMM_SMEM>>>(
        src_feat, W_src, p_Psrc, N_SRC);                       // W_src[:128]
    tf32_gemm_kernel<<<(N_DST + 127) / 128, 256, GEMM_SMEM>>>(
        dst_feat, W_dst, p_nh, N_DST);
    tf32_gemm_kernel<<<E_NUM / 128, 256, GEMM_SMEM>>>(
        edge_feat, W_src + F_IN * HD, p_Pe, E_NUM);            // W_src[128:]

    // fused online-softmax aggregation
    aggregate_kernel<<<N_DST, 128>>>(src_idx, bias, out);
}